// round 9
// baseline (speedup 1.0000x reference)
#include <cuda_runtime.h>
#include <cuda_bf16.h>

// ---------------------------------------------------------------------------
// Sequential logistic-regression SGD, restructured as:
//   per chunk of B samples:  z_s = b_s - sum_{u<s} c_u * G[u,s]
//                            c_u = LR*(sigmoid(z_u) - y_u)
//                            theta -= X_chunk^T c
// Gram triangles G (data-only) are precomputed fully in parallel; the
// sequential kernel is a single persistent block (no inter-block sync).
// ---------------------------------------------------------------------------

#define F        1024
#define NTRAIN   32768
#define B        256
#define NCH      (NTRAIN / B)     // 128 chunks per epoch
#define EPOCHS   2
#define ITERS    (NCH * EPOCHS)   // 256
#define LR       0.01f
#define TRI      ((B * (B - 1)) / 2)   // 32640 packed upper-tri elements

// Packed strict-upper-triangle Gram per chunk: G[u][s], u<s, at
//   index tribase(u) + (s - u - 1),  tribase(u) = u*(2B-1-u)/2
__device__ float g_tri_glob[(size_t)NCH * TRI];   // ~16.7 MB

// ---------------------------------------------------------------------------
// Gram kernel: 64x64 output tiles, 256 threads, 4x4 micro-tile, K-tile 16.
// Only tiles with ti <= tj are computed (10 of 16 per chunk).
// ---------------------------------------------------------------------------
__constant__ int c_ti[10] = {0,0,0,0,1,1,1,2,2,3};
__constant__ int c_tj[10] = {0,1,2,3,1,2,3,2,3,3};

#define TDIM  64
#define KTILE 16
#define APAD  68   // 68*4 bytes: keeps 16B alignment for v4 LDS, spreads banks

__global__ __launch_bounds__(256) void gram_kernel(const float* __restrict__ X)
{
    __shared__ __align__(16) float As[KTILE][APAD];
    __shared__ __align__(16) float Bs[KTILE][APAD];

    const int bx  = blockIdx.x;
    const int k   = bx / 10;          // chunk
    const int t   = bx - k * 10;      // tile id
    const int ti  = c_ti[t], tj = c_tj[t];
    const int cb  = k * B;
    const int rowA = cb + ti * TDIM;
    const int rowB = cb + tj * TDIM;

    const int tid = threadIdx.x;      // 256
    const int kl  = tid & 15;         // k within tile for loads
    const int m0  = tid >> 4;         // 0..15
    const int tx  = tid & 15;         // output col group
    const int ty  = tid >> 4;         // output row group

    float acc[4][4];
#pragma unroll
    for (int i = 0; i < 4; i++)
#pragma unroll
        for (int j = 0; j < 4; j++) acc[i][j] = 0.f;

    for (int kk = 0; kk < F; kk += KTILE) {
#pragma unroll
        for (int mm = 0; mm < 4; mm++) {
            int m = m0 + 16 * mm;
            As[kl][m] = X[(size_t)(rowA + m) * F + kk + kl];
            Bs[kl][m] = X[(size_t)(rowB + m) * F + kk + kl];
        }
        __syncthreads();
#pragma unroll
        for (int kq = 0; kq < KTILE; kq++) {
            float a0 = As[kq][4 * ty + 0];
            float a1 = As[kq][4 * ty + 1];
            float a2 = As[kq][4 * ty + 2];
            float a3 = As[kq][4 * ty + 3];
            float b0 = Bs[kq][4 * tx + 0];
            float b1 = Bs[kq][4 * tx + 1];
            float b2 = Bs[kq][4 * tx + 2];
            float b3 = Bs[kq][4 * tx + 3];
            acc[0][0] += a0 * b0; acc[0][1] += a0 * b1; acc[0][2] += a0 * b2; acc[0][3] += a0 * b3;
            acc[1][0] += a1 * b0; acc[1][1] += a1 * b1; acc[1][2] += a1 * b2; acc[1][3] += a1 * b3;
            acc[2][0] += a2 * b0; acc[2][1] += a2 * b1; acc[2][2] += a2 * b2; acc[2][3] += a2 * b3;
            acc[3][0] += a3 * b0; acc[3][1] += a3 * b1; acc[3][2] += a3 * b2; acc[3][3] += a3 * b3;
        }
        __syncthreads();
    }

    // Epilogue: packed strict-upper-triangle store
    float* gdst = g_tri_glob + (size_t)k * TRI;
#pragma unroll
    for (int ii = 0; ii < 4; ii++) {
        int u  = ti * TDIM + 4 * ty + ii;
        int bu = (u * (2 * B - 1 - u)) / 2 - u - 1;   // so idx = bu + s
#pragma unroll
        for (int jj = 0; jj < 4; jj++) {
            int s = tj * TDIM + 4 * tx + jj;
            if (u < s) gdst[bu + s] = acc[ii][jj];
        }
    }
}

// ---------------------------------------------------------------------------
// Sequential kernel: one block, 1024 threads.
//   smem: [gs: TRI][ths: F][bs: B][cs: B][ys: B]  = 137728 bytes
// ---------------------------------------------------------------------------
__global__ __launch_bounds__(1024, 1) void seq_kernel(
    const float* __restrict__ X,
    const float* __restrict__ label,
    const float* __restrict__ theta0,
    float* __restrict__ out)
{
    extern __shared__ float sm[];
    float* gs  = sm;              // TRI
    float* ths = sm + TRI;        // F
    float* bs  = ths + F;         // B
    float* cs  = bs + B;          // B
    float* ys  = cs + B;          // B

    const int tid  = threadIdx.x;   // 0..1023
    const int lane = tid & 31;
    const int wid  = tid >> 5;

    ths[tid] = theta0[tid];
    __syncthreads();

    for (int it = 0; it < ITERS; it++) {
        const int k  = it & (NCH - 1);
        const int cb = k * B;

        // --- stage Gram triangle (float4 flat copy) + scaled labels ---
        {
            const float4* gsrc = (const float4*)(g_tri_glob + (size_t)k * TRI);
            float4*       gdst = (float4*)gs;
            for (int i = tid; i < TRI / 4; i += 1024) gdst[i] = gsrc[i];
            if (tid < B) ys[tid] = LR * label[cb + tid];
        }
        __syncthreads();

        // --- b phase: b[s] = dot(theta, x_s); warp wid handles rows wid*8..+7
        {
            const float4* th4 = (const float4*)ths;
#pragma unroll 1
            for (int q = 0; q < 8; q++) {
                int s = wid * 8 + q;
                const float4* xr = (const float4*)(X + (size_t)(cb + s) * F);
                float acc = 0.f;
#pragma unroll
                for (int t2 = 0; t2 < 8; t2++) {
                    float4 xv = xr[lane + 32 * t2];
                    float4 tv = th4[lane + 32 * t2];
                    acc += xv.x * tv.x + xv.y * tv.y + xv.z * tv.z + xv.w * tv.w;
                }
#pragma unroll
                for (int o = 16; o; o >>= 1)
                    acc += __shfl_down_sync(0xffffffffu, acc, o);
                if (lane == 0) bs[s] = acc;
            }
        }
        __syncthreads();

        // --- sequential chain on warp 0 ---
        if (wid == 0) {
            float z[8], yv[8];
#pragma unroll
            for (int r = 0; r < 8; r++) {
                z[r]  = bs[lane + 32 * r];
                yv[r] = ys[lane + 32 * r];
            }
            int base = 0;
#pragma unroll 1
            for (int r = 0; r < 8; r++) {
#pragma unroll 4
                for (int lu = 0; lu < 32; lu++) {
                    int u   = r * 32 + lu;
                    int off = base - u - 1;
                    // prefetch G row segment (independent of c -> hides LDS lat)
                    float g[8];
#pragma unroll
                    for (int rr = 0; rr < 8; rr++) {
                        int idx = off + lane + 32 * rr;
                        idx = idx < 0 ? 0 : idx;
                        g[rr] = gs[idx];
                    }
                    // critical path: z -> sigmoid -> c -> broadcast -> apply
                    float sig = 1.f / (1.f + __expf(-z[r]));
                    float cv  = LR * sig - yv[r];
                    float c   = __shfl_sync(0xffffffffu, cv, lu);
                    if (lane == 0) cs[u] = c;
#pragma unroll
                    for (int rr = 0; rr < 8; rr++) {
                        int s = lane + 32 * rr;
                        if (s > u) z[rr] -= c * g[rr];
                    }
                    base += B - 1 - u;
                }
            }
        }
        __syncthreads();

        // --- theta update: theta[f] -= sum_s c[s] * X[cb+s][f] ---
        {
            float tl = ths[tid];
            const float* xc = X + (size_t)cb * F;
#pragma unroll 8
            for (int s = 0; s < B; s++) {
                tl -= cs[s] * xc[(size_t)s * F + tid];
            }
            ths[tid] = tl;
        }
        // next iteration's stage-barrier orders ths writes before b-phase reads
    }
    __syncthreads();
    out[tid] = ths[tid];
}

// ---------------------------------------------------------------------------
extern "C" void kernel_launch(void* const* d_in, const int* in_sizes, int n_in,
                              void* d_out, int out_size)
{
    const float* data  = (const float*)d_in[0];   // [32768, 1024] f32
    const float* label = (const float*)d_in[1];   // [32768] f32
    const float* theta = (const float*)d_in[2];   // [1024] f32
    float*       out   = (float*)d_out;           // [1024] f32

    const int smem_bytes = (TRI + F + 3 * B) * (int)sizeof(float);  // 137728
    cudaFuncSetAttribute(seq_kernel,
                         cudaFuncAttributeMaxDynamicSharedMemorySize,
                         smem_bytes);

    gram_kernel<<<NCH * 10, 256>>>(data);
    seq_kernel<<<1, 1024, smem_bytes>>>(data, label, theta, out);
}

// round 10
// speedup vs baseline: 1.0618x; 1.0618x over previous
#include <cuda_runtime.h>
#include <cuda_bf16.h>

// ---------------------------------------------------------------------------
// Sequential logistic-regression SGD, restructured with overlap:
//   chain:   z_s = b_s - sum_{u<s} c_u * G_k[u,s],  c_u = LR*(sigmoid(z_u)-y_u)
//   b-recursion: b^(k+1) = X_{k+1} theta_{k-1}  -  CG_k^T c^(k)
//                 (p := X_{k+1} theta_{k-1} computed DURING chain k by engine warps,
//                  theta update for chunk k-1 also deferred into chain k's shadow)
// G (within-chunk Gram, row-major full) and CG (consecutive-chunk cross-Gram,
// stored transposed CGT[j][s][u]) depend only on the data -> precomputed by
// grid-wide GEMM kernels.
// ---------------------------------------------------------------------------

#define F        1024
#define NTRAIN   32768
#define B        256
#define NCH      (NTRAIN / B)     // 128 chunks per epoch
#define EPOCHS   2
#define ITERS    (NCH * EPOCHS)   // 256
#define LR       0.01f

// Full per-chunk Gram, row-major: gfull[k][u][s] = x_u . x_s (only u<s used).
// Tail pad 4096 floats: chain prefetches up to row u+8 (past row 255).
__device__ float gfull_glob[(size_t)NCH * B * B + 4096];   // ~33.6 MB
// Cross-Gram transposed: cgt[j][s][u] = x^{(j+1)&127}_s . x^{(j)}_u
__device__ float cgt_glob[(size_t)NCH * B * B];            // ~33.6 MB

// ---------------------------------------------------------------------------
// Shared GEMM tile config: 64x64 tiles, 256 threads, 4x4 micro-tile, K-tile 16
// ---------------------------------------------------------------------------
#define TDIM  64
#define KTILE 16
#define APAD  68   // 272 bytes/row = 17*16 -> float4 LDS stays 16B aligned

__constant__ int c_ti[10] = {0,0,0,0,1,1,1,2,2,3};
__constant__ int c_tj[10] = {0,1,2,3,1,2,3,2,3,3};

// --- within-chunk Gram: only ti<=tj tiles (10 per chunk) -------------------
__global__ __launch_bounds__(256) void gram_kernel(const float* __restrict__ X)
{
    __shared__ __align__(16) float As[KTILE][APAD];
    __shared__ __align__(16) float Bs[KTILE][APAD];

    const int bx = blockIdx.x;
    const int k  = bx / 10;
    const int t  = bx - k * 10;
    const int ti = c_ti[t], tj = c_tj[t];
    const int rowA = k * B + ti * TDIM;   // u rows
    const int rowB = k * B + tj * TDIM;   // s rows

    const int tid = threadIdx.x;
    const int kl  = tid & 15;
    const int m0  = tid >> 4;
    const int tx  = tid & 15;
    const int ty  = tid >> 4;

    float acc[4][4];
#pragma unroll
    for (int i = 0; i < 4; i++)
#pragma unroll
        for (int j = 0; j < 4; j++) acc[i][j] = 0.f;

    for (int kk = 0; kk < F; kk += KTILE) {
#pragma unroll
        for (int mm = 0; mm < 4; mm++) {
            int m = m0 + 16 * mm;
            As[kl][m] = X[(size_t)(rowA + m) * F + kk + kl];
            Bs[kl][m] = X[(size_t)(rowB + m) * F + kk + kl];
        }
        __syncthreads();
#pragma unroll
        for (int kq = 0; kq < KTILE; kq++) {
            float4 a4 = *(const float4*)&As[kq][4 * ty];
            float4 b4 = *(const float4*)&Bs[kq][4 * tx];
            acc[0][0] += a4.x * b4.x; acc[0][1] += a4.x * b4.y; acc[0][2] += a4.x * b4.z; acc[0][3] += a4.x * b4.w;
            acc[1][0] += a4.y * b4.x; acc[1][1] += a4.y * b4.y; acc[1][2] += a4.y * b4.z; acc[1][3] += a4.y * b4.w;
            acc[2][0] += a4.z * b4.x; acc[2][1] += a4.z * b4.y; acc[2][2] += a4.z * b4.z; acc[2][3] += a4.z * b4.w;
            acc[3][0] += a4.w * b4.x; acc[3][1] += a4.w * b4.y; acc[3][2] += a4.w * b4.z; acc[3][3] += a4.w * b4.w;
        }
        __syncthreads();
    }

    float* gd = gfull_glob + ((size_t)k << 16);
#pragma unroll
    for (int ii = 0; ii < 4; ii++) {
        int u = ti * TDIM + 4 * ty + ii;
#pragma unroll
        for (int jj = 0; jj < 4; jj++) {
            int s = tj * TDIM + 4 * tx + jj;
            gd[(u << 8) + s] = acc[ii][jj];   // only u<s consumed; rest harmless
        }
    }
}

// --- cross-Gram: full 16 tiles per consecutive-chunk pair ------------------
__global__ __launch_bounds__(256) void cross_gram_kernel(const float* __restrict__ X)
{
    __shared__ __align__(16) float As[KTILE][APAD];
    __shared__ __align__(16) float Bs[KTILE][APAD];

    const int bx = blockIdx.x;
    const int j  = bx >> 4;
    const int t  = bx & 15;
    const int ti = t >> 2, tj = t & 3;
    const int rowA = (((j + 1) & 127) << 8) + ti * TDIM;  // s rows (next chunk)
    const int rowB = (j << 8) + tj * TDIM;                // u rows (chunk j)

    const int tid = threadIdx.x;
    const int kl  = tid & 15;
    const int m0  = tid >> 4;
    const int tx  = tid & 15;
    const int ty  = tid >> 4;

    float acc[4][4];
#pragma unroll
    for (int i = 0; i < 4; i++)
#pragma unroll
        for (int jj = 0; jj < 4; jj++) acc[i][jj] = 0.f;

    for (int kk = 0; kk < F; kk += KTILE) {
#pragma unroll
        for (int mm = 0; mm < 4; mm++) {
            int m = m0 + 16 * mm;
            As[kl][m] = X[(size_t)(rowA + m) * F + kk + kl];
            Bs[kl][m] = X[(size_t)(rowB + m) * F + kk + kl];
        }
        __syncthreads();
#pragma unroll
        for (int kq = 0; kq < KTILE; kq++) {
            float4 a4 = *(const float4*)&As[kq][4 * ty];
            float4 b4 = *(const float4*)&Bs[kq][4 * tx];
            acc[0][0] += a4.x * b4.x; acc[0][1] += a4.x * b4.y; acc[0][2] += a4.x * b4.z; acc[0][3] += a4.x * b4.w;
            acc[1][0] += a4.y * b4.x; acc[1][1] += a4.y * b4.y; acc[1][2] += a4.y * b4.z; acc[1][3] += a4.y * b4.w;
            acc[2][0] += a4.z * b4.x; acc[2][1] += a4.z * b4.y; acc[2][2] += a4.z * b4.z; acc[2][3] += a4.z * b4.w;
            acc[3][0] += a4.w * b4.x; acc[3][1] += a4.w * b4.y; acc[3][2] += a4.w * b4.z; acc[3][3] += a4.w * b4.w;
        }
        __syncthreads();
    }

    float* cd = cgt_glob + ((size_t)j << 16);
#pragma unroll
    for (int ii = 0; ii < 4; ii++) {
        int s = ti * TDIM + 4 * ty + ii;
#pragma unroll
        for (int jj = 0; jj < 4; jj++) {
            int u = tj * TDIM + 4 * tx + jj;
            cd[((size_t)s << 8) + u] = acc[ii][jj];
        }
    }
}

// ---------------------------------------------------------------------------
// Sequential kernel: one block, 544 threads (warp 0 = chain, warps 1..16 =
// engine doing deferred theta-update + next p-matvec under the chain).
// ---------------------------------------------------------------------------
#define NT 544

__global__ __launch_bounds__(NT, 1) void seq_kernel(
    const float* __restrict__ X,
    const float* __restrict__ label,
    const float* __restrict__ theta0,
    float* __restrict__ out)
{
    __shared__ __align__(16) float ths[F];
    __shared__ __align__(16) float bs[B];
    __shared__ __align__(16) float ps[B];
    __shared__ __align__(16) float csb[2][B];
    __shared__ __align__(16) float ysb[2][B];

    const int tid  = threadIdx.x;
    const int lane = tid & 31;
    const int wid  = tid >> 5;

    ths[tid] = theta0[tid];
    if (tid + NT < F) ths[tid + NT] = theta0[tid + NT];
    __syncthreads();

    // ---- prologue: b0 = X_0 . theta_init, ys for chunk 0 ----
    {
        const float4* th4 = (const float4*)ths;
#pragma unroll 1
        for (int j2 = 0; j2 < 16; j2++) {
            int s = wid + 17 * j2;
            if (s < B) {
                const float4* xr = (const float4*)(X + (size_t)s * F);
                float acc = 0.f;
#pragma unroll
                for (int t = 0; t < 8; t++) {
                    float4 xv = xr[lane + 32 * t];
                    float4 tv = th4[lane + 32 * t];
                    acc += xv.x * tv.x + xv.y * tv.y + xv.z * tv.z + xv.w * tv.w;
                }
#pragma unroll
                for (int o = 16; o; o >>= 1)
                    acc += __shfl_down_sync(0xffffffffu, acc, o);
                if (lane == 0) bs[s] = acc;
            }
        }
        if (tid < B) ysb[0][tid] = LR * label[tid];
    }
    __syncthreads();

    for (int it = 0; it < ITERS; it++) {
        const int k = it & 127;

        if (wid == 0) {
            // ================= chain for chunk k =================
            // lane owns samples s = lane*8 + rr (consecutive -> 2x LDG.128 / step)
            const float* yb = ysb[it & 1];
            float*       cw = csb[it & 1];
            const float* gf = gfull_glob + ((size_t)k << 16);

            float z[8], yv[8];
#pragma unroll
            for (int rr = 0; rr < 8; rr++) {
                z[rr]  = bs[lane * 8 + rr];
                yv[rr] = yb[lane * 8 + rr];
            }
            // 8-deep register prefetch of G rows (data-independent addresses)
            float4 gA[8], gB[8];
            {
                const float4* p0 = (const float4*)(gf + lane * 8);
#pragma unroll
                for (int d = 0; d < 8; d++) {
                    gA[d] = p0[d * 64];
                    gB[d] = p0[d * 64 + 1];
                }
            }
            int u = 0;
#pragma unroll 1
            for (int blk = 0; blk < 32; blk++) {
#pragma unroll
                for (int q = 0; q < 8; q++) {      // u = blk*8 + q, slot = q
                    // critical path: z[q] -> sigmoid -> c -> shfl -> z update
                    float e   = __expf(-z[q]);
                    float sig = 1.f / (1.f + e);
                    float cv  = LR * sig - yv[q];
                    float c   = __shfl_sync(0xffffffffu, cv, u >> 3);
                    if (lane == 0) cw[u] = c;
                    int s0 = lane * 8;
                    if (s0 + 0 > u) z[0] -= c * gA[q].x;
                    if (s0 + 1 > u) z[1] -= c * gA[q].y;
                    if (s0 + 2 > u) z[2] -= c * gA[q].z;
                    if (s0 + 3 > u) z[3] -= c * gA[q].w;
                    if (s0 + 4 > u) z[4] -= c * gB[q].x;
                    if (s0 + 5 > u) z[5] -= c * gB[q].y;
                    if (s0 + 6 > u) z[6] -= c * gB[q].z;
                    if (s0 + 7 > u) z[7] -= c * gB[q].w;
                    // prefetch row u+8 (tail pad covers overflow past row 255)
                    const float4* pp =
                        (const float4*)(gf + (((size_t)(u + 8)) << 8) + lane * 8);
                    gA[q] = pp[0];
                    gB[q] = pp[1];
                    u++;
                }
            }
        } else {
            // ================= engine (warps 1..16) =================
            const int et = tid - 32;    // 0..511
            const int ew = wid - 1;     // 0..15

            // deferred theta update for chunk (it-1): theta -= X^T c_prev
            if (it > 0) {
                const float* cp = csb[(it - 1) & 1];
                const float* xb = X + (((size_t)((it - 1) & 127)) << 8) * F;
                float t0 = ths[et];
                float t1 = ths[et + 512];
#pragma unroll 4
                for (int s = 0; s < B; s++) {
                    float c = cp[s];
                    const float* xr = xb + (size_t)s * F;
                    t0 -= c * xr[et];
                    t1 -= c * xr[et + 512];
                }
                ths[et]       = t0;
                ths[et + 512] = t1;
            }
            // engine-only barrier: theta writes visible before p-matvec reads
            asm volatile("bar.sync 1, 512;" ::: "memory");

            // p = X_{(it+1)&127} . theta   (theta == theta_{it-1} here)
            {
                const int kn = (it + 1) & 127;
                const float*  xb  = X + (((size_t)kn) << 8) * F;
                const float4* th4 = (const float4*)ths;
#pragma unroll 1
                for (int q = 0; q < 16; q++) {
                    int s = ew * 16 + q;
                    const float4* xr = (const float4*)(xb + (size_t)s * F);
                    float acc = 0.f;
#pragma unroll
                    for (int t = 0; t < 8; t++) {
                        float4 xv = xr[lane + 32 * t];
                        float4 tv = th4[lane + 32 * t];
                        acc += xv.x * tv.x + xv.y * tv.y + xv.z * tv.z + xv.w * tv.w;
                    }
#pragma unroll
                    for (int o = 16; o; o >>= 1)
                        acc += __shfl_down_sync(0xffffffffu, acc, o);
                    if (lane == 0) ps[s] = acc;
                }
                if (et < B)
                    ysb[(it + 1) & 1][et] = LR * label[((size_t)kn << 8) + et];
            }
        }
        __syncthreads();

        // ---- b^(it+1) = ps - CG_k^T c^(it)  (all 17 warps, skip on last) ----
        if (it < ITERS - 1) {
            const float* cc = csb[it & 1];
            const float* cg = cgt_glob + ((size_t)k << 16);
#pragma unroll 1
            for (int j2 = 0; j2 < 16; j2++) {
                int s = wid + 17 * j2;
                if (s < B) {
                    const float* row = cg + ((size_t)s << 8);
                    float acc = 0.f;
#pragma unroll
                    for (int t = 0; t < 8; t++)
                        acc += cc[lane + 32 * t] * row[lane + 32 * t];
#pragma unroll
                    for (int o = 16; o; o >>= 1)
                        acc += __shfl_down_sync(0xffffffffu, acc, o);
                    if (lane == 0) bs[s] = ps[s] - acc;
                }
            }
        }
        __syncthreads();
    }

    // ---- final deferred theta update (chunk 127, c^(255)) + output ----
    {
        const float* cp = csb[(ITERS - 1) & 1];
        const float* xb = X + (((size_t)127) << 8) * F;
        const bool hi = (tid + NT) < F;
        float t0 = ths[tid];
        float t1 = hi ? ths[tid + NT] : 0.f;
#pragma unroll 4
        for (int s = 0; s < B; s++) {
            float c = cp[s];
            const float* xr = xb + (size_t)s * F;
            t0 -= c * xr[tid];
            if (hi) t1 -= c * xr[tid + NT];
        }
        out[tid] = t0;
        if (hi) out[tid + NT] = t1;
    }
}

// ---------------------------------------------------------------------------
extern "C" void kernel_launch(void* const* d_in, const int* in_sizes, int n_in,
                              void* d_out, int out_size)
{
    const float* data  = (const float*)d_in[0];   // [32768, 1024] f32
    const float* label = (const float*)d_in[1];   // [32768] f32
    const float* theta = (const float*)d_in[2];   // [1024] f32
    float*       out   = (float*)d_out;           // [1024] f32

    gram_kernel<<<NCH * 10, 256>>>(data);
    cross_gram_kernel<<<NCH * 16, 256>>>(data);
    seq_kernel<<<1, NT>>>(data, label, theta, out);
}